// round 2
// baseline (speedup 1.0000x reference)
#include <cuda_runtime.h>
#include <cuda_bf16.h>
#include <math.h>

#define N_ATOMS 1000000
#define N_EDGES 4000000
#define NGRAPH  1024
#define IN_F    64
#define HF      32
#define LN_EPS  1e-5f

// -------- scratch (device globals: no allocation allowed) --------
__device__ float g_deg_out[N_ATOMS];
__device__ float g_deg_in[N_ATOMS];
__device__ float g_ns[N_ATOMS];
__device__ float g_nd[N_ATOMS];
__device__ float g_h [N_ATOMS * HF];   // node features after each stage
__device__ float g_hs[N_ATOMS * HF];   // h * ns  (pre-normalized messages)
__device__ float g_m [N_ATOMS * HF];   // scatter accumulator

// -------- helpers --------
__device__ __forceinline__ float warp_sum(float v) {
    #pragma unroll
    for (int o = 16; o > 0; o >>= 1) v += __shfl_xor_sync(0xffffffffu, v, o);
    return v;
}
__device__ __forceinline__ float elu1(float x) {
    return x > 0.f ? x : expm1f(x);
}

// -------- zeroing kernels --------
__global__ void zero_deg_kernel() {
    int i = blockIdx.x * blockDim.x + threadIdx.x;
    if (i < N_ATOMS) { g_deg_out[i] = 0.f; g_deg_in[i] = 0.f; }
}
__global__ void zero_m_kernel() {
    size_t i = (size_t)blockIdx.x * blockDim.x + threadIdx.x;
    size_t stride = (size_t)gridDim.x * blockDim.x;
    for (; i < (size_t)N_ATOMS * HF; i += stride) g_m[i] = 0.f;
}
__global__ void zero_out_kernel(float* out) {
    int i = blockIdx.x * blockDim.x + threadIdx.x;
    if (i < NGRAPH) out[i] = 0.f;
}

// -------- degree + norm --------
__global__ void degree_kernel(const int* __restrict__ src, const int* __restrict__ dst) {
    int e = blockIdx.x * blockDim.x + threadIdx.x;
    if (e < N_EDGES) {
        atomicAdd(&g_deg_out[src[e]], 1.f);
        atomicAdd(&g_deg_in [dst[e]], 1.f);
    }
}
__global__ void norm_kernel() {
    int i = blockIdx.x * blockDim.x + threadIdx.x;
    if (i < N_ATOMS) {
        float dout = g_deg_out[i], din = g_deg_in[i];
        g_ns[i] = dout > 0.f ? rsqrtf(dout) : 0.f;
        g_nd[i] = din  > 0.f ? rsqrtf(din)  : 0.f;
    }
}

// -------- input MLP: h = elu(LN(feats@w0+b0)); hs = h*ns --------
__global__ void input_mlp_kernel(const float* __restrict__ feats,
                                 const float* __restrict__ w0,
                                 const float* __restrict__ b0,
                                 const float* __restrict__ g0,
                                 const float* __restrict__ be0) {
    __shared__ float sw[IN_F * HF];
    for (int i = threadIdx.x; i < IN_F * HF; i += blockDim.x) sw[i] = w0[i];
    __syncthreads();

    int node = blockIdx.x * (blockDim.x >> 5) + (threadIdx.x >> 5);
    int lane = threadIdx.x & 31;
    if (node >= N_ATOMS) return;

    const float* x = feats + (size_t)node * IN_F;
    float x0 = x[lane], x1 = x[lane + 32];

    float acc = b0[lane];
    #pragma unroll
    for (int k = 0; k < 32; k++) {
        float xk = __shfl_sync(0xffffffffu, x0, k);
        acc = fmaf(xk, sw[k * HF + lane], acc);
    }
    #pragma unroll
    for (int k = 0; k < 32; k++) {
        float xk = __shfl_sync(0xffffffffu, x1, k);
        acc = fmaf(xk, sw[(k + 32) * HF + lane], acc);
    }
    // LayerNorm over 32 lanes
    float mu  = warp_sum(acc) * (1.f / HF);
    float d   = acc - mu;
    float var = warp_sum(d * d) * (1.f / HF);
    float y   = d * rsqrtf(var + LN_EPS) * g0[lane] + be0[lane];
    float h   = elu1(y);

    size_t off = (size_t)node * HF + lane;
    g_h [off] = h;
    g_hs[off] = h * g_ns[node];
}

// -------- edge scatter: m[dst] += hs[src]  (8 threads/edge, float4) --------
__global__ void scatter_kernel(const int* __restrict__ src, const int* __restrict__ dst) {
    long long idx = (long long)blockIdx.x * blockDim.x + threadIdx.x;
    if (idx >= (long long)N_EDGES * 8) return;
    int e = (int)(idx >> 3);
    int p = ((int)idx & 7) * 4;
    int s = __ldg(&src[e]);
    int d = __ldg(&dst[e]);
    float4 v = *reinterpret_cast<const float4*>(&g_hs[(size_t)s * HF + p]);
    float* mp = &g_m[(size_t)d * HF + p];
    atomicAdd(mp + 0, v.x);
    atomicAdd(mp + 1, v.y);
    atomicAdd(mp + 2, v.z);
    atomicAdd(mp + 3, v.w);
}

// -------- conv epilogue + node MLP block --------
// h = elu(LN(elu((m*nd)@wc + bc)@w + b)); hs = h*ns
__global__ void node_block_kernel(const float* __restrict__ wc,
                                  const float* __restrict__ bc,
                                  const float* __restrict__ w,
                                  const float* __restrict__ b,
                                  const float* __restrict__ g,
                                  const float* __restrict__ be) {
    __shared__ float swc[HF * HF];
    __shared__ float sw [HF * HF];
    for (int i = threadIdx.x; i < HF * HF; i += blockDim.x) { swc[i] = wc[i]; sw[i] = w[i]; }
    __syncthreads();

    int node = blockIdx.x * (blockDim.x >> 5) + (threadIdx.x >> 5);
    int lane = threadIdx.x & 31;
    if (node >= N_ATOMS) return;

    size_t off = (size_t)node * HF + lane;
    float mval = g_m[off] * g_nd[node];

    // t = elu(m @ wc + bc)
    float t = bc[lane];
    #pragma unroll
    for (int k = 0; k < 32; k++) {
        float mk = __shfl_sync(0xffffffffu, mval, k);
        t = fmaf(mk, swc[k * HF + lane], t);
    }
    t = elu1(t);

    // u = t @ w + b ; LN ; elu
    float u = b[lane];
    #pragma unroll
    for (int k = 0; k < 32; k++) {
        float tk = __shfl_sync(0xffffffffu, t, k);
        u = fmaf(tk, sw[k * HF + lane], u);
    }
    float mu  = warp_sum(u) * (1.f / HF);
    float d   = u - mu;
    float var = warp_sum(d * d) * (1.f / HF);
    float y   = d * rsqrtf(var + LN_EPS) * g[lane] + be[lane];
    float h   = elu1(y);

    g_h [off] = h;
    g_hs[off] = h * g_ns[node];
}

// -------- head: out[gid] += elu(h @ wout + bout) --------
__global__ void head_kernel(const float* __restrict__ wout,
                            const float* __restrict__ bout,
                            const int* __restrict__ gid,
                            float* __restrict__ out) {
    __shared__ float sacc[NGRAPH];
    __shared__ float swout[HF];
    for (int i = threadIdx.x; i < NGRAPH; i += blockDim.x) sacc[i] = 0.f;
    if (threadIdx.x < HF) swout[threadIdx.x] = wout[threadIdx.x];
    __syncthreads();

    int i = blockIdx.x * blockDim.x + threadIdx.x;
    if (i < N_ATOMS) {
        const float* hp = &g_h[(size_t)i * HF];
        float acc = bout[0];
        #pragma unroll
        for (int k = 0; k < 32; k += 4) {
            float4 hv = *reinterpret_cast<const float4*>(&hp[k]);
            acc = fmaf(hv.x, swout[k+0], acc);
            acc = fmaf(hv.y, swout[k+1], acc);
            acc = fmaf(hv.z, swout[k+2], acc);
            acc = fmaf(hv.w, swout[k+3], acc);
        }
        float v = elu1(acc);
        atomicAdd(&sacc[gid[i]], v);
    }
    __syncthreads();
    for (int j = threadIdx.x; j < NGRAPH; j += blockDim.x) {
        float v = sacc[j];
        if (v != 0.f) atomicAdd(&out[j], v);
    }
}

// -------- launch --------
extern "C" void kernel_launch(void* const* d_in, const int* in_sizes, int n_in,
                              void* d_out, int out_size) {
    const float* feats = (const float*)d_in[0];
    const int*   src   = (const int*)  d_in[1];
    const int*   dst   = (const int*)  d_in[2];
    const int*   gid   = (const int*)  d_in[3];
    const float* w0    = (const float*)d_in[4];
    const float* b0    = (const float*)d_in[5];
    const float* g0    = (const float*)d_in[6];
    const float* be0   = (const float*)d_in[7];
    const float* wc1   = (const float*)d_in[8];
    const float* bc1   = (const float*)d_in[9];
    const float* w1    = (const float*)d_in[10];
    const float* b1    = (const float*)d_in[11];
    const float* g1    = (const float*)d_in[12];
    const float* be1   = (const float*)d_in[13];
    const float* wc2   = (const float*)d_in[14];
    const float* bc2   = (const float*)d_in[15];
    const float* w2    = (const float*)d_in[16];
    const float* b2    = (const float*)d_in[17];
    const float* g2    = (const float*)d_in[18];
    const float* be2   = (const float*)d_in[19];
    const float* wout  = (const float*)d_in[20];
    const float* bout  = (const float*)d_in[21];
    float* out = (float*)d_out;

    const int TPB = 256;
    const int WPB = TPB / 32;
    int node_blocks_t = (N_ATOMS + TPB - 1) / TPB;           // thread-per-node
    int node_blocks_w = (N_ATOMS + WPB - 1) / WPB;           // warp-per-node
    int edge_blocks   = (N_EDGES + TPB - 1) / TPB;
    long long sc_threads = (long long)N_EDGES * 8;
    int sc_blocks = (int)((sc_threads + TPB - 1) / TPB);

    // degrees + norms
    zero_deg_kernel<<<node_blocks_t, TPB>>>();
    degree_kernel<<<edge_blocks, TPB>>>(src, dst);
    norm_kernel<<<node_blocks_t, TPB>>>();

    // input MLP
    input_mlp_kernel<<<node_blocks_w, TPB>>>(feats, w0, b0, g0, be0);

    // block 1
    zero_m_kernel<<<4096, TPB>>>();
    scatter_kernel<<<sc_blocks, TPB>>>(src, dst);
    node_block_kernel<<<node_blocks_w, TPB>>>(wc1, bc1, w1, b1, g1, be1);

    // block 2
    zero_m_kernel<<<4096, TPB>>>();
    scatter_kernel<<<sc_blocks, TPB>>>(src, dst);
    node_block_kernel<<<node_blocks_w, TPB>>>(wc2, bc2, w2, b2, g2, be2);

    // head + readout
    zero_out_kernel<<<(NGRAPH + TPB - 1) / TPB, TPB>>>(out);
    head_kernel<<<node_blocks_t, TPB>>>(wout, bout, gid, out);
}

// round 3
// speedup vs baseline: 1.2723x; 1.2723x over previous
#include <cuda_runtime.h>
#include <cuda_bf16.h>
#include <math.h>

#define N_ATOMS 1000000
#define N_EDGES 4000000
#define NGRAPH  1024
#define IN_F    64
#define HF      32
#define LN_EPS  1e-5f
#define TILE    64            // nodes per block in tiled kernels
#define XS_STR  68            // shared row stride for 64-col tile (conflict-free scalar reads)
#define MS_STR  36            // shared row stride for 32-col tiles

// -------- scratch (device globals: zero-initialized at module load) --------
__device__ float g_deg_out[N_ATOMS];
__device__ float g_deg_in[N_ATOMS];
__device__ float g_ns[N_ATOMS];
__device__ float g_nd[N_ATOMS];
__device__ float g_h [N_ATOMS * HF];   // final node features (read by head only)
__device__ float g_hs[N_ATOMS * HF];   // h * ns  (messages for scatter)
__device__ float g_m [N_ATOMS * HF];   // scatter accumulator (invariant: all-zero between launches)

// -------- helpers --------
__device__ __forceinline__ float elu1(float x) { return x > 0.f ? x : expm1f(x); }
__device__ __forceinline__ float sum8(float v) {
    v += __shfl_xor_sync(0xffffffffu, v, 1);
    v += __shfl_xor_sync(0xffffffffu, v, 2);
    v += __shfl_xor_sync(0xffffffffu, v, 4);
    return v;
}

// -------- zero degrees (vectorized) --------
__global__ void zero_deg_kernel() {
    int i = blockIdx.x * blockDim.x + threadIdx.x;
    if (i < N_ATOMS / 4) {
        reinterpret_cast<float4*>(g_deg_out)[i] = make_float4(0.f, 0.f, 0.f, 0.f);
        reinterpret_cast<float4*>(g_deg_in )[i] = make_float4(0.f, 0.f, 0.f, 0.f);
    }
}
__global__ void zero_out_kernel(float* out) {
    int i = blockIdx.x * blockDim.x + threadIdx.x;
    if (i < NGRAPH) out[i] = 0.f;
}

// -------- degree + norm --------
__global__ void degree_kernel(const int* __restrict__ src, const int* __restrict__ dst) {
    int e = blockIdx.x * blockDim.x + threadIdx.x;
    if (e < N_EDGES) {
        atomicAdd(&g_deg_out[src[e]], 1.f);
        atomicAdd(&g_deg_in [dst[e]], 1.f);
    }
}
__global__ void norm_kernel() {
    int i = blockIdx.x * blockDim.x + threadIdx.x;
    if (i < N_ATOMS) {
        float dout = g_deg_out[i], din = g_deg_in[i];
        g_ns[i] = dout > 0.f ? rsqrtf(dout) : 0.f;
        g_nd[i] = din  > 0.f ? rsqrtf(din)  : 0.f;
    }
}

// -------- input MLP (tiled): g_hs = elu(LN(feats@w0+b0)) * ns --------
// 256 threads, 64 nodes per block. thread = (nq [0..31], oq [0..7]);
// handles nodes {nq, nq+32}, output cols [4*oq, 4*oq+4).
__global__ __launch_bounds__(256) void input_mlp_tile(
        const float* __restrict__ feats,
        const float* __restrict__ w0,  const float* __restrict__ b0,
        const float* __restrict__ g0,  const float* __restrict__ be0) {
    __shared__ float xs[TILE * XS_STR];
    __shared__ float sw[IN_F * HF];
    int t = threadIdx.x;
    int base = blockIdx.x * TILE;

    for (int i = t; i < IN_F * HF; i += 256) sw[i] = w0[i];
    const float4* fp = reinterpret_cast<const float4*>(feats + (size_t)base * IN_F);
    #pragma unroll
    for (int i = t; i < TILE * (IN_F / 4); i += 256) {           // 1024 float4
        int n = i >> 4, c = i & 15;
        *reinterpret_cast<float4*>(&xs[n * XS_STR + c * 4]) = fp[(size_t)n * 16 + c];
    }
    __syncthreads();

    int oq = t & 7, nq = t >> 3;
    float4 bv = reinterpret_cast<const float4*>(b0)[oq];
    float4 a0 = bv, a1 = bv;
    const float* x0 = &xs[nq * XS_STR];
    const float* x1 = &xs[(nq + 32) * XS_STR];
    #pragma unroll
    for (int k = 0; k < IN_F; k += 4) {
        float4 wv0 = *reinterpret_cast<const float4*>(&sw[(k+0) * HF + oq * 4]);
        float4 wv1 = *reinterpret_cast<const float4*>(&sw[(k+1) * HF + oq * 4]);
        float4 wv2 = *reinterpret_cast<const float4*>(&sw[(k+2) * HF + oq * 4]);
        float4 wv3 = *reinterpret_cast<const float4*>(&sw[(k+3) * HF + oq * 4]);
        float p0 = x0[k], p1 = x0[k+1], p2 = x0[k+2], p3 = x0[k+3];
        float q0 = x1[k], q1 = x1[k+1], q2 = x1[k+2], q3 = x1[k+3];
        a0.x = fmaf(p0, wv0.x, a0.x); a0.y = fmaf(p0, wv0.y, a0.y); a0.z = fmaf(p0, wv0.z, a0.z); a0.w = fmaf(p0, wv0.w, a0.w);
        a0.x = fmaf(p1, wv1.x, a0.x); a0.y = fmaf(p1, wv1.y, a0.y); a0.z = fmaf(p1, wv1.z, a0.z); a0.w = fmaf(p1, wv1.w, a0.w);
        a0.x = fmaf(p2, wv2.x, a0.x); a0.y = fmaf(p2, wv2.y, a0.y); a0.z = fmaf(p2, wv2.z, a0.z); a0.w = fmaf(p2, wv2.w, a0.w);
        a0.x = fmaf(p3, wv3.x, a0.x); a0.y = fmaf(p3, wv3.y, a0.y); a0.z = fmaf(p3, wv3.z, a0.z); a0.w = fmaf(p3, wv3.w, a0.w);
        a1.x = fmaf(q0, wv0.x, a1.x); a1.y = fmaf(q0, wv0.y, a1.y); a1.z = fmaf(q0, wv0.z, a1.z); a1.w = fmaf(q0, wv0.w, a1.w);
        a1.x = fmaf(q1, wv1.x, a1.x); a1.y = fmaf(q1, wv1.y, a1.y); a1.z = fmaf(q1, wv1.z, a1.z); a1.w = fmaf(q1, wv1.w, a1.w);
        a1.x = fmaf(q2, wv2.x, a1.x); a1.y = fmaf(q2, wv2.y, a1.y); a1.z = fmaf(q2, wv2.z, a1.z); a1.w = fmaf(q2, wv2.w, a1.w);
        a1.x = fmaf(q3, wv3.x, a1.x); a1.y = fmaf(q3, wv3.y, a1.y); a1.z = fmaf(q3, wv3.z, a1.z); a1.w = fmaf(q3, wv3.w, a1.w);
    }

    // LayerNorm + ELU + *ns, for both nodes
    float4 gv  = reinterpret_cast<const float4*>(g0)[oq];
    float4 bev = reinterpret_cast<const float4*>(be0)[oq];
    #pragma unroll
    for (int nn = 0; nn < 2; nn++) {
        float4 a = nn ? a1 : a0;
        int node = base + nq + nn * 32;
        float mu = sum8(a.x + a.y + a.z + a.w) * (1.f / HF);
        float dx = a.x - mu, dy = a.y - mu, dz = a.z - mu, dw = a.w - mu;
        float var = sum8(dx*dx + dy*dy + dz*dz + dw*dw) * (1.f / HF);
        float r = rsqrtf(var + LN_EPS);
        float s = g_ns[node];
        float4 o;
        o.x = elu1(dx * r * gv.x + bev.x) * s;
        o.y = elu1(dy * r * gv.y + bev.y) * s;
        o.z = elu1(dz * r * gv.z + bev.z) * s;
        o.w = elu1(dw * r * gv.w + bev.w) * s;
        *reinterpret_cast<float4*>(&g_hs[(size_t)node * HF + oq * 4]) = o;
    }
}

// -------- edge scatter: m[dst] += hs[src], vectorized RED --------
__global__ void scatter_kernel(const int* __restrict__ src, const int* __restrict__ dst) {
    long long idx = (long long)blockIdx.x * blockDim.x + threadIdx.x;
    if (idx >= (long long)N_EDGES * 8) return;
    int e = (int)(idx >> 3);
    int p = ((int)idx & 7) * 4;
    int s = __ldg(&src[e]);
    int d = __ldg(&dst[e]);
    float4 v = __ldg(reinterpret_cast<const float4*>(&g_hs[(size_t)s * HF + p]));
    float* mp = &g_m[(size_t)d * HF + p];
    asm volatile("red.global.add.v4.f32 [%0], {%1, %2, %3, %4};"
                 :: "l"(mp), "f"(v.x), "f"(v.y), "f"(v.z), "f"(v.w) : "memory");
}

// -------- conv epilogue + node MLP block (tiled) --------
// out = elu(LN(elu((m*nd)@wc + bc)@w + b)) * (use_ns ? ns : 1);  also zeroes g_m.
__global__ __launch_bounds__(256) void node_block_tile(
        const float* __restrict__ wc, const float* __restrict__ bc,
        const float* __restrict__ w,  const float* __restrict__ b,
        const float* __restrict__ g,  const float* __restrict__ be,
        float* __restrict__ outbuf, int use_ns) {
    __shared__ float ms[TILE * MS_STR];
    __shared__ float ts[TILE * MS_STR];
    __shared__ float swc[HF * HF];
    __shared__ float sw [HF * HF];
    int t = threadIdx.x;
    int base = blockIdx.x * TILE;

    for (int i = t; i < HF * HF; i += 256) { swc[i] = wc[i]; sw[i] = w[i]; }
    // load m tile (scaled by nd) and write zeros back (restores all-zero invariant)
    #pragma unroll
    for (int i = t; i < TILE * (HF / 4); i += 256) {             // 512 float4
        int n = i >> 3, c = i & 7;
        float4* gp = reinterpret_cast<float4*>(&g_m[(size_t)(base + n) * HF + c * 4]);
        float4 v = *gp;
        float ndv = g_nd[base + n];
        v.x *= ndv; v.y *= ndv; v.z *= ndv; v.w *= ndv;
        *reinterpret_cast<float4*>(&ms[n * MS_STR + c * 4]) = v;
        *gp = make_float4(0.f, 0.f, 0.f, 0.f);
    }
    __syncthreads();

    int oq = t & 7, nq = t >> 3;

    // GEMM1: t = elu(ms @ wc + bc)
    {
        float4 bv = reinterpret_cast<const float4*>(bc)[oq];
        float4 a0 = bv, a1 = bv;
        const float* x0 = &ms[nq * MS_STR];
        const float* x1 = &ms[(nq + 32) * MS_STR];
        #pragma unroll
        for (int k = 0; k < HF; k += 4) {
            float4 wv0 = *reinterpret_cast<const float4*>(&swc[(k+0) * HF + oq * 4]);
            float4 wv1 = *reinterpret_cast<const float4*>(&swc[(k+1) * HF + oq * 4]);
            float4 wv2 = *reinterpret_cast<const float4*>(&swc[(k+2) * HF + oq * 4]);
            float4 wv3 = *reinterpret_cast<const float4*>(&swc[(k+3) * HF + oq * 4]);
            float p0 = x0[k], p1 = x0[k+1], p2 = x0[k+2], p3 = x0[k+3];
            float q0 = x1[k], q1 = x1[k+1], q2 = x1[k+2], q3 = x1[k+3];
            a0.x = fmaf(p0, wv0.x, a0.x); a0.y = fmaf(p0, wv0.y, a0.y); a0.z = fmaf(p0, wv0.z, a0.z); a0.w = fmaf(p0, wv0.w, a0.w);
            a0.x = fmaf(p1, wv1.x, a0.x); a0.y = fmaf(p1, wv1.y, a0.y); a0.z = fmaf(p1, wv1.z, a0.z); a0.w = fmaf(p1, wv1.w, a0.w);
            a0.x = fmaf(p2, wv2.x, a0.x); a0.y = fmaf(p2, wv2.y, a0.y); a0.z = fmaf(p2, wv2.z, a0.z); a0.w = fmaf(p2, wv2.w, a0.w);
            a0.x = fmaf(p3, wv3.x, a0.x); a0.y = fmaf(p3, wv3.y, a0.y); a0.z = fmaf(p3, wv3.z, a0.z); a0.w = fmaf(p3, wv3.w, a0.w);
            a1.x = fmaf(q0, wv0.x, a1.x); a1.y = fmaf(q0, wv0.y, a1.y); a1.z = fmaf(q0, wv0.z, a1.z); a1.w = fmaf(q0, wv0.w, a1.w);
            a1.x = fmaf(q1, wv1.x, a1.x); a1.y = fmaf(q1, wv1.y, a1.y); a1.z = fmaf(q1, wv1.z, a1.z); a1.w = fmaf(q1, wv1.w, a1.w);
            a1.x = fmaf(q2, wv2.x, a1.x); a1.y = fmaf(q2, wv2.y, a1.y); a1.z = fmaf(q2, wv2.z, a1.z); a1.w = fmaf(q2, wv2.w, a1.w);
            a1.x = fmaf(q3, wv3.x, a1.x); a1.y = fmaf(q3, wv3.y, a1.y); a1.z = fmaf(q3, wv3.z, a1.z); a1.w = fmaf(q3, wv3.w, a1.w);
        }
        float4 o0, o1;
        o0.x = elu1(a0.x); o0.y = elu1(a0.y); o0.z = elu1(a0.z); o0.w = elu1(a0.w);
        o1.x = elu1(a1.x); o1.y = elu1(a1.y); o1.z = elu1(a1.z); o1.w = elu1(a1.w);
        *reinterpret_cast<float4*>(&ts[nq * MS_STR + oq * 4]) = o0;
        *reinterpret_cast<float4*>(&ts[(nq + 32) * MS_STR + oq * 4]) = o1;
    }
    __syncthreads();

    // GEMM2: u = ts @ w + b ; LN ; ELU ; scale ; store
    {
        float4 bv = reinterpret_cast<const float4*>(b)[oq];
        float4 a0 = bv, a1 = bv;
        const float* x0 = &ts[nq * MS_STR];
        const float* x1 = &ts[(nq + 32) * MS_STR];
        #pragma unroll
        for (int k = 0; k < HF; k += 4) {
            float4 wv0 = *reinterpret_cast<const float4*>(&sw[(k+0) * HF + oq * 4]);
            float4 wv1 = *reinterpret_cast<const float4*>(&sw[(k+1) * HF + oq * 4]);
            float4 wv2 = *reinterpret_cast<const float4*>(&sw[(k+2) * HF + oq * 4]);
            float4 wv3 = *reinterpret_cast<const float4*>(&sw[(k+3) * HF + oq * 4]);
            float p0 = x0[k], p1 = x0[k+1], p2 = x0[k+2], p3 = x0[k+3];
            float q0 = x1[k], q1 = x1[k+1], q2 = x1[k+2], q3 = x1[k+3];
            a0.x = fmaf(p0, wv0.x, a0.x); a0.y = fmaf(p0, wv0.y, a0.y); a0.z = fmaf(p0, wv0.z, a0.z); a0.w = fmaf(p0, wv0.w, a0.w);
            a0.x = fmaf(p1, wv1.x, a0.x); a0.y = fmaf(p1, wv1.y, a0.y); a0.z = fmaf(p1, wv1.z, a0.z); a0.w = fmaf(p1, wv1.w, a0.w);
            a0.x = fmaf(p2, wv2.x, a0.x); a0.y = fmaf(p2, wv2.y, a0.y); a0.z = fmaf(p2, wv2.z, a0.z); a0.w = fmaf(p2, wv2.w, a0.w);
            a0.x = fmaf(p3, wv3.x, a0.x); a0.y = fmaf(p3, wv3.y, a0.y); a0.z = fmaf(p3, wv3.z, a0.z); a0.w = fmaf(p3, wv3.w, a0.w);
            a1.x = fmaf(q0, wv0.x, a1.x); a1.y = fmaf(q0, wv0.y, a1.y); a1.z = fmaf(q0, wv0.z, a1.z); a1.w = fmaf(q0, wv0.w, a1.w);
            a1.x = fmaf(q1, wv1.x, a1.x); a1.y = fmaf(q1, wv1.y, a1.y); a1.z = fmaf(q1, wv1.z, a1.z); a1.w = fmaf(q1, wv1.w, a1.w);
            a1.x = fmaf(q2, wv2.x, a1.x); a1.y = fmaf(q2, wv2.y, a1.y); a1.z = fmaf(q2, wv2.z, a1.z); a1.w = fmaf(q2, wv2.w, a1.w);
            a1.x = fmaf(q3, wv3.x, a1.x); a1.y = fmaf(q3, wv3.y, a1.y); a1.z = fmaf(q3, wv3.z, a1.z); a1.w = fmaf(q3, wv3.w, a1.w);
        }
        float4 gv  = reinterpret_cast<const float4*>(g)[oq];
        float4 bev = reinterpret_cast<const float4*>(be)[oq];
        #pragma unroll
        for (int nn = 0; nn < 2; nn++) {
            float4 a = nn ? a1 : a0;
            int node = base + nq + nn * 32;
            float mu = sum8(a.x + a.y + a.z + a.w) * (1.f / HF);
            float dx = a.x - mu, dy = a.y - mu, dz = a.z - mu, dw = a.w - mu;
            float var = sum8(dx*dx + dy*dy + dz*dz + dw*dw) * (1.f / HF);
            float r = rsqrtf(var + LN_EPS);
            float s = use_ns ? g_ns[node] : 1.f;
            float4 o;
            o.x = elu1(dx * r * gv.x + bev.x) * s;
            o.y = elu1(dy * r * gv.y + bev.y) * s;
            o.z = elu1(dz * r * gv.z + bev.z) * s;
            o.w = elu1(dw * r * gv.w + bev.w) * s;
            *reinterpret_cast<float4*>(&outbuf[(size_t)node * HF + oq * 4]) = o;
        }
    }
}

// -------- head: out[gid] += elu(h @ wout + bout) --------
__global__ void head_kernel(const float* __restrict__ wout,
                            const float* __restrict__ bout,
                            const int* __restrict__ gid,
                            float* __restrict__ out) {
    __shared__ float sacc[NGRAPH];
    __shared__ float swout[HF];
    for (int i = threadIdx.x; i < NGRAPH; i += blockDim.x) sacc[i] = 0.f;
    if (threadIdx.x < HF) swout[threadIdx.x] = wout[threadIdx.x];
    __syncthreads();

    int i = blockIdx.x * blockDim.x + threadIdx.x;
    if (i < N_ATOMS) {
        const float* hp = &g_h[(size_t)i * HF];
        float acc = bout[0];
        #pragma unroll
        for (int k = 0; k < HF; k += 4) {
            float4 hv = *reinterpret_cast<const float4*>(&hp[k]);
            acc = fmaf(hv.x, swout[k+0], acc);
            acc = fmaf(hv.y, swout[k+1], acc);
            acc = fmaf(hv.z, swout[k+2], acc);
            acc = fmaf(hv.w, swout[k+3], acc);
        }
        atomicAdd(&sacc[gid[i]], elu1(acc));
    }
    __syncthreads();
    for (int j = threadIdx.x; j < NGRAPH; j += blockDim.x) {
        float v = sacc[j];
        if (v != 0.f) atomicAdd(&out[j], v);
    }
}

// -------- launch --------
extern "C" void kernel_launch(void* const* d_in, const int* in_sizes, int n_in,
                              void* d_out, int out_size) {
    const float* feats = (const float*)d_in[0];
    const int*   src   = (const int*)  d_in[1];
    const int*   dst   = (const int*)  d_in[2];
    const int*   gid   = (const int*)  d_in[3];
    const float* w0    = (const float*)d_in[4];
    const float* b0    = (const float*)d_in[5];
    const float* g0    = (const float*)d_in[6];
    const float* be0   = (const float*)d_in[7];
    const float* wc1   = (const float*)d_in[8];
    const float* bc1   = (const float*)d_in[9];
    const float* w1    = (const float*)d_in[10];
    const float* b1    = (const float*)d_in[11];
    const float* g1    = (const float*)d_in[12];
    const float* be1   = (const float*)d_in[13];
    const float* wc2   = (const float*)d_in[14];
    const float* bc2   = (const float*)d_in[15];
    const float* w2    = (const float*)d_in[16];
    const float* b2    = (const float*)d_in[17];
    const float* g2    = (const float*)d_in[18];
    const float* be2   = (const float*)d_in[19];
    const float* wout  = (const float*)d_in[20];
    const float* bout  = (const float*)d_in[21];
    float* out = (float*)d_out;

    float* d_hs; cudaGetSymbolAddress((void**)&d_hs, g_hs);
    float* d_h;  cudaGetSymbolAddress((void**)&d_h,  g_h);

    const int TPB = 256;
    int tile_blocks = N_ATOMS / TILE;                       // 15625
    int node_blocks = (N_ATOMS + TPB - 1) / TPB;
    int edge_blocks = (N_EDGES + TPB - 1) / TPB;
    long long sc_threads = (long long)N_EDGES * 8;
    int sc_blocks = (int)((sc_threads + TPB - 1) / TPB);

    // degrees + norms
    zero_deg_kernel<<<(N_ATOMS / 4 + TPB - 1) / TPB, TPB>>>();
    degree_kernel<<<edge_blocks, TPB>>>(src, dst);
    norm_kernel<<<node_blocks, TPB>>>();

    // input MLP -> g_hs
    input_mlp_tile<<<tile_blocks, TPB>>>(feats, w0, b0, g0, be0);

    // block 1 (g_m zeroed inside node_block_tile)
    scatter_kernel<<<sc_blocks, TPB>>>(src, dst);
    node_block_tile<<<tile_blocks, TPB>>>(wc1, bc1, w1, b1, g1, be1, d_hs, 1);

    // block 2
    scatter_kernel<<<sc_blocks, TPB>>>(src, dst);
    node_block_tile<<<tile_blocks, TPB>>>(wc2, bc2, w2, b2, g2, be2, d_h, 0);

    // head + readout
    zero_out_kernel<<<(NGRAPH + TPB - 1) / TPB, TPB>>>(out);
    head_kernel<<<node_blocks, TPB>>>(wout, bout, gid, out);
}

// round 5
// speedup vs baseline: 2.2894x; 1.7995x over previous
#include <cuda_runtime.h>
#include <cuda_fp16.h>
#include <cuda_bf16.h>
#include <math.h>

#define N_ATOMS 1000000
#define N_EDGES 4000000
#define NGRAPH  1024
#define IN_F    64
#define HF      32
#define LN_EPS  1e-5f
#define TILE    64            // nodes per block in tiled kernels
#define XS_STR  68            // shared row stride for 64-col tile
#define MS_STR  36            // shared row stride for 32-col tiles

// -------- scratch (device globals: zero-initialized at module load) --------
__device__ float  g_deg_out[N_ATOMS];
__device__ float  g_deg_in[N_ATOMS];
__device__ float  g_ns[N_ATOMS];
__device__ float  g_nd[N_ATOMS];
__device__ float  g_h [N_ATOMS * HF];    // final node features (read by head only)
__device__ __half g_hs[N_ATOMS * HF];    // h * ns  (fp16 messages)
__device__ __half g_m [N_ATOMS * HF];    // fp16 scatter accumulator (all-zero invariant)

// -------- helpers --------
__device__ __forceinline__ float elu1(float x) { return x > 0.f ? x : expm1f(x); }
__device__ __forceinline__ float sum8(float v) {
    v += __shfl_xor_sync(0xffffffffu, v, 1);
    v += __shfl_xor_sync(0xffffffffu, v, 2);
    v += __shfl_xor_sync(0xffffffffu, v, 4);
    return v;
}

// -------- zero degrees (vectorized) --------
__global__ void zero_deg_kernel() {
    int i = blockIdx.x * blockDim.x + threadIdx.x;
    if (i < N_ATOMS / 4) {
        reinterpret_cast<float4*>(g_deg_out)[i] = make_float4(0.f, 0.f, 0.f, 0.f);
        reinterpret_cast<float4*>(g_deg_in )[i] = make_float4(0.f, 0.f, 0.f, 0.f);
    }
}
__global__ void zero_out_kernel(float* out) {
    int i = blockIdx.x * blockDim.x + threadIdx.x;
    if (i < NGRAPH) out[i] = 0.f;
}

// -------- degree + norm --------
__global__ void degree_kernel(const int* __restrict__ src, const int* __restrict__ dst) {
    int e = blockIdx.x * blockDim.x + threadIdx.x;
    if (e < N_EDGES) {
        atomicAdd(&g_deg_out[src[e]], 1.f);
        atomicAdd(&g_deg_in [dst[e]], 1.f);
    }
}
__global__ void norm_kernel() {
    int i = blockIdx.x * blockDim.x + threadIdx.x;
    if (i < N_ATOMS) {
        float dout = g_deg_out[i], din = g_deg_in[i];
        g_ns[i] = dout > 0.f ? rsqrtf(dout) : 0.f;
        g_nd[i] = din  > 0.f ? rsqrtf(din)  : 0.f;
    }
}

// store 4 consecutive floats as 4 halves (8B) at hs row offset
__device__ __forceinline__ void store_h4(__half* p, float a, float b, float c, float d) {
    __half2 lo = __floats2half2_rn(a, b);
    __half2 hi = __floats2half2_rn(c, d);
    uint2 v;
    v.x = *reinterpret_cast<unsigned*>(&lo);
    v.y = *reinterpret_cast<unsigned*>(&hi);
    *reinterpret_cast<uint2*>(p) = v;
}

// -------- input MLP (tiled): g_hs = half(elu(LN(feats@w0+b0)) * ns) --------
__global__ __launch_bounds__(256) void input_mlp_tile(
        const float* __restrict__ feats,
        const float* __restrict__ w0,  const float* __restrict__ b0,
        const float* __restrict__ g0,  const float* __restrict__ be0) {
    __shared__ float xs[TILE * XS_STR];
    __shared__ float sw[IN_F * HF];
    int t = threadIdx.x;
    int base = blockIdx.x * TILE;

    for (int i = t; i < IN_F * HF; i += 256) sw[i] = w0[i];
    const float4* fp = reinterpret_cast<const float4*>(feats + (size_t)base * IN_F);
    #pragma unroll
    for (int i = t; i < TILE * (IN_F / 4); i += 256) {
        int n = i >> 4, c = i & 15;
        *reinterpret_cast<float4*>(&xs[n * XS_STR + c * 4]) = fp[(size_t)n * 16 + c];
    }
    __syncthreads();

    int oq = t & 7, nq = t >> 3;
    float4 bv = reinterpret_cast<const float4*>(b0)[oq];
    float4 a0 = bv, a1 = bv;
    const float* x0 = &xs[nq * XS_STR];
    const float* x1 = &xs[(nq + 32) * XS_STR];
    #pragma unroll
    for (int k = 0; k < IN_F; k += 4) {
        float4 wv0 = *reinterpret_cast<const float4*>(&sw[(k+0) * HF + oq * 4]);
        float4 wv1 = *reinterpret_cast<const float4*>(&sw[(k+1) * HF + oq * 4]);
        float4 wv2 = *reinterpret_cast<const float4*>(&sw[(k+2) * HF + oq * 4]);
        float4 wv3 = *reinterpret_cast<const float4*>(&sw[(k+3) * HF + oq * 4]);
        float p0 = x0[k], p1 = x0[k+1], p2 = x0[k+2], p3 = x0[k+3];
        float q0 = x1[k], q1 = x1[k+1], q2 = x1[k+2], q3 = x1[k+3];
        a0.x = fmaf(p0, wv0.x, a0.x); a0.y = fmaf(p0, wv0.y, a0.y); a0.z = fmaf(p0, wv0.z, a0.z); a0.w = fmaf(p0, wv0.w, a0.w);
        a0.x = fmaf(p1, wv1.x, a0.x); a0.y = fmaf(p1, wv1.y, a0.y); a0.z = fmaf(p1, wv1.z, a0.z); a0.w = fmaf(p1, wv1.w, a0.w);
        a0.x = fmaf(p2, wv2.x, a0.x); a0.y = fmaf(p2, wv2.y, a0.y); a0.z = fmaf(p2, wv2.z, a0.z); a0.w = fmaf(p2, wv2.w, a0.w);
        a0.x = fmaf(p3, wv3.x, a0.x); a0.y = fmaf(p3, wv3.y, a0.y); a0.z = fmaf(p3, wv3.z, a0.z); a0.w = fmaf(p3, wv3.w, a0.w);
        a1.x = fmaf(q0, wv0.x, a1.x); a1.y = fmaf(q0, wv0.y, a1.y); a1.z = fmaf(q0, wv0.z, a1.z); a1.w = fmaf(q0, wv0.w, a1.w);
        a1.x = fmaf(q1, wv1.x, a1.x); a1.y = fmaf(q1, wv1.y, a1.y); a1.z = fmaf(q1, wv1.z, a1.z); a1.w = fmaf(q1, wv1.w, a1.w);
        a1.x = fmaf(q2, wv2.x, a1.x); a1.y = fmaf(q2, wv2.y, a1.y); a1.z = fmaf(q2, wv2.z, a1.z); a1.w = fmaf(q2, wv2.w, a1.w);
        a1.x = fmaf(q3, wv3.x, a1.x); a1.y = fmaf(q3, wv3.y, a1.y); a1.z = fmaf(q3, wv3.z, a1.z); a1.w = fmaf(q3, wv3.w, a1.w);
    }

    float4 gv  = reinterpret_cast<const float4*>(g0)[oq];
    float4 bev = reinterpret_cast<const float4*>(be0)[oq];
    #pragma unroll
    for (int nn = 0; nn < 2; nn++) {
        float4 a = nn ? a1 : a0;
        int node = base + nq + nn * 32;
        float mu = sum8(a.x + a.y + a.z + a.w) * (1.f / HF);
        float dx = a.x - mu, dy = a.y - mu, dz = a.z - mu, dw = a.w - mu;
        float var = sum8(dx*dx + dy*dy + dz*dz + dw*dw) * (1.f / HF);
        float r = rsqrtf(var + LN_EPS);
        float s = g_ns[node];
        store_h4(&g_hs[(size_t)node * HF + oq * 4],
                 elu1(dx * r * gv.x + bev.x) * s,
                 elu1(dy * r * gv.y + bev.y) * s,
                 elu1(dz * r * gv.z + bev.z) * s,
                 elu1(dw * r * gv.w + bev.w) * s);
    }
}

// -------- edge scatter: m[dst] += hs[src]  (4 threads/edge, v4.f16x2 RED) --------
__global__ void scatter_kernel(const int* __restrict__ src, const int* __restrict__ dst) {
    long long idx = (long long)blockIdx.x * blockDim.x + threadIdx.x;
    if (idx >= (long long)N_EDGES * 4) return;
    int e = (int)(idx >> 2);
    int p = ((int)idx & 3) * 8;           // half offset: 0,8,16,24
    int s = __ldg(&src[e]);
    int d = __ldg(&dst[e]);
    uint4 v = __ldg(reinterpret_cast<const uint4*>(&g_hs[(size_t)s * HF + p]));
    __half* mp = &g_m[(size_t)d * HF + p];
    asm volatile("red.global.add.noftz.v4.f16x2 [%0], {%1, %2, %3, %4};"
                 :: "l"(mp), "r"(v.x), "r"(v.y), "r"(v.z), "r"(v.w) : "memory");
}

// -------- conv epilogue + node MLP block (tiled) --------
// MODE 0: out -> g_hs (half, scaled by ns). MODE 1: out -> g_h (float). Zeroes g_m.
template<int MODE>
__global__ __launch_bounds__(256) void node_block_tile(
        const float* __restrict__ wc, const float* __restrict__ bc,
        const float* __restrict__ w,  const float* __restrict__ b,
        const float* __restrict__ g,  const float* __restrict__ be) {
    __shared__ float ms[TILE * MS_STR];
    __shared__ float ts[TILE * MS_STR];
    __shared__ float swc[HF * HF];
    __shared__ float sw [HF * HF];
    int t = threadIdx.x;
    int base = blockIdx.x * TILE;

    for (int i = t; i < HF * HF; i += 256) { swc[i] = wc[i]; sw[i] = w[i]; }
    // load m tile (half -> float, *nd) and restore all-zero invariant
    {
        int n = t >> 2, c = t & 3;                     // 256 threads = 64 nodes x 4 chunks
        uint4* gp = reinterpret_cast<uint4*>(&g_m[(size_t)(base + n) * HF + c * 8]);
        uint4 v = *gp;
        float ndv = g_nd[base + n];
        float* mrow = &ms[n * MS_STR + c * 8];
        __half2 h;
        h = *reinterpret_cast<__half2*>(&v.x); float2 f0 = __half22float2(h);
        h = *reinterpret_cast<__half2*>(&v.y); float2 f1 = __half22float2(h);
        h = *reinterpret_cast<__half2*>(&v.z); float2 f2 = __half22float2(h);
        h = *reinterpret_cast<__half2*>(&v.w); float2 f3 = __half22float2(h);
        mrow[0] = f0.x * ndv; mrow[1] = f0.y * ndv;
        mrow[2] = f1.x * ndv; mrow[3] = f1.y * ndv;
        mrow[4] = f2.x * ndv; mrow[5] = f2.y * ndv;
        mrow[6] = f3.x * ndv; mrow[7] = f3.y * ndv;
        *gp = make_uint4(0u, 0u, 0u, 0u);
    }
    __syncthreads();

    int oq = t & 7, nq = t >> 3;

    // GEMM1: ts = elu(ms @ wc + bc)
    {
        float4 bv = reinterpret_cast<const float4*>(bc)[oq];
        float4 a0 = bv, a1 = bv;
        const float* x0 = &ms[nq * MS_STR];
        const float* x1 = &ms[(nq + 32) * MS_STR];
        #pragma unroll
        for (int k = 0; k < HF; k += 4) {
            float4 wv0 = *reinterpret_cast<const float4*>(&swc[(k+0) * HF + oq * 4]);
            float4 wv1 = *reinterpret_cast<const float4*>(&swc[(k+1) * HF + oq * 4]);
            float4 wv2 = *reinterpret_cast<const float4*>(&swc[(k+2) * HF + oq * 4]);
            float4 wv3 = *reinterpret_cast<const float4*>(&swc[(k+3) * HF + oq * 4]);
            float p0 = x0[k], p1 = x0[k+1], p2 = x0[k+2], p3 = x0[k+3];
            float q0 = x1[k], q1 = x1[k+1], q2 = x1[k+2], q3 = x1[k+3];
            a0.x = fmaf(p0, wv0.x, a0.x); a0.y = fmaf(p0, wv0.y, a0.y); a0.z = fmaf(p0, wv0.z, a0.z); a0.w = fmaf(p0, wv0.w, a0.w);
            a0.x = fmaf(p1, wv1.x, a0.x); a0.y = fmaf(p1, wv1.y, a0.y); a0.z = fmaf(p1, wv1.z, a0.z); a0.w = fmaf(p1, wv1.w, a0.w);
            a0.x = fmaf(p2, wv2.x, a0.x); a0.y = fmaf(p2, wv2.y, a0.y); a0.z = fmaf(p2, wv2.z, a0.z); a0.w = fmaf(p2, wv2.w, a0.w);
            a0.x = fmaf(p3, wv3.x, a0.x); a0.y = fmaf(p3, wv3.y, a0.y); a0.z = fmaf(p3, wv3.z, a0.z); a0.w = fmaf(p3, wv3.w, a0.w);
            a1.x = fmaf(q0, wv0.x, a1.x); a1.y = fmaf(q0, wv0.y, a1.y); a1.z = fmaf(q0, wv0.z, a1.z); a1.w = fmaf(q0, wv0.w, a1.w);
            a1.x = fmaf(q1, wv1.x, a1.x); a1.y = fmaf(q1, wv1.y, a1.y); a1.z = fmaf(q1, wv1.z, a1.z); a1.w = fmaf(q1, wv1.w, a1.w);
            a1.x = fmaf(q2, wv2.x, a1.x); a1.y = fmaf(q2, wv2.y, a1.y); a1.z = fmaf(q2, wv2.z, a1.z); a1.w = fmaf(q2, wv2.w, a1.w);
            a1.x = fmaf(q3, wv3.x, a1.x); a1.y = fmaf(q3, wv3.y, a1.y); a1.z = fmaf(q3, wv3.z, a1.z); a1.w = fmaf(q3, wv3.w, a1.w);
        }
        float4 o0, o1;
        o0.x = elu1(a0.x); o0.y = elu1(a0.y); o0.z = elu1(a0.z); o0.w = elu1(a0.w);
        o1.x = elu1(a1.x); o1.y = elu1(a1.y); o1.z = elu1(a1.z); o1.w = elu1(a1.w);
        *reinterpret_cast<float4*>(&ts[nq * MS_STR + oq * 4]) = o0;
        *reinterpret_cast<float4*>(&ts[(nq + 32) * MS_STR + oq * 4]) = o1;
    }
    __syncthreads();

    // GEMM2: u = ts @ w + b ; LN ; ELU ; scale ; store
    {
        float4 bv = reinterpret_cast<const float4*>(b)[oq];
        float4 a0 = bv, a1 = bv;
        const float* x0 = &ts[nq * MS_STR];
        const float* x1 = &ts[(nq + 32) * MS_STR];
        #pragma unroll
        for (int k = 0; k < HF; k += 4) {
            float4 wv0 = *reinterpret_cast<const float4*>(&sw[(k+0) * HF + oq * 4]);
            float4 wv1 = *reinterpret_cast<const float4*>(&sw[(k+1) * HF + oq * 4]);
            float4 wv2 = *reinterpret_cast<const float4*>(&sw[(k+2) * HF + oq * 4]);
            float4 wv3 = *reinterpret_cast<const float4*>(&sw[(k+3) * HF + oq * 4]);
            float p0 = x0[k], p1 = x0[k+1], p2 = x0[k+2], p3 = x0[k+3];
            float q0 = x1[k], q1 = x1[k+1], q2 = x1[k+2], q3 = x1[k+3];
            a0.x = fmaf(p0, wv0.x, a0.x); a0.y = fmaf(p0, wv0.y, a0.y); a0.z = fmaf(p0, wv0.z, a0.z); a0.w = fmaf(p0, wv0.w, a0.w);
            a0.x = fmaf(p1, wv1.x, a0.x); a0.y = fmaf(p1, wv1.y, a0.y); a0.z = fmaf(p1, wv1.z, a0.z); a0.w = fmaf(p1, wv1.w, a0.w);
            a0.x = fmaf(p2, wv2.x, a0.x); a0.y = fmaf(p2, wv2.y, a0.y); a0.z = fmaf(p2, wv2.z, a0.z); a0.w = fmaf(p2, wv2.w, a0.w);
            a0.x = fmaf(p3, wv3.x, a0.x); a0.y = fmaf(p3, wv3.y, a0.y); a0.z = fmaf(p3, wv3.z, a0.z); a0.w = fmaf(p3, wv3.w, a0.w);
            a1.x = fmaf(q0, wv0.x, a1.x); a1.y = fmaf(q0, wv0.y, a1.y); a1.z = fmaf(q0, wv0.z, a1.z); a1.w = fmaf(q0, wv0.w, a1.w);
            a1.x = fmaf(q1, wv1.x, a1.x); a1.y = fmaf(q1, wv1.y, a1.y); a1.z = fmaf(q1, wv1.z, a1.z); a1.w = fmaf(q1, wv1.w, a1.w);
            a1.x = fmaf(q2, wv2.x, a1.x); a1.y = fmaf(q2, wv2.y, a1.y); a1.z = fmaf(q2, wv2.z, a1.z); a1.w = fmaf(q2, wv2.w, a1.w);
            a1.x = fmaf(q3, wv3.x, a1.x); a1.y = fmaf(q3, wv3.y, a1.y); a1.z = fmaf(q3, wv3.z, a1.z); a1.w = fmaf(q3, wv3.w, a1.w);
        }
        float4 gv  = reinterpret_cast<const float4*>(g)[oq];
        float4 bev = reinterpret_cast<const float4*>(be)[oq];
        #pragma unroll
        for (int nn = 0; nn < 2; nn++) {
            float4 a = nn ? a1 : a0;
            int node = base + nq + nn * 32;
            float mu = sum8(a.x + a.y + a.z + a.w) * (1.f / HF);
            float dx = a.x - mu, dy = a.y - mu, dz = a.z - mu, dw = a.w - mu;
            float var = sum8(dx*dx + dy*dy + dz*dz + dw*dw) * (1.f / HF);
            float r = rsqrtf(var + LN_EPS);
            if (MODE == 0) {
                float s = g_ns[node];
                store_h4(&g_hs[(size_t)node * HF + oq * 4],
                         elu1(dx * r * gv.x + bev.x) * s,
                         elu1(dy * r * gv.y + bev.y) * s,
                         elu1(dz * r * gv.z + bev.z) * s,
                         elu1(dw * r * gv.w + bev.w) * s);
            } else {
                float4 o;
                o.x = elu1(dx * r * gv.x + bev.x);
                o.y = elu1(dy * r * gv.y + bev.y);
                o.z = elu1(dz * r * gv.z + bev.z);
                o.w = elu1(dw * r * gv.w + bev.w);
                *reinterpret_cast<float4*>(&g_h[(size_t)node * HF + oq * 4]) = o;
            }
        }
    }
}

// -------- head: out[gid] += elu(h @ wout + bout) --------
__global__ void head_kernel(const float* __restrict__ wout,
                            const float* __restrict__ bout,
                            const int* __restrict__ gid,
                            float* __restrict__ out) {
    __shared__ float sacc[NGRAPH];
    __shared__ float swout[HF];
    for (int i = threadIdx.x; i < NGRAPH; i += blockDim.x) sacc[i] = 0.f;
    if (threadIdx.x < HF) swout[threadIdx.x] = wout[threadIdx.x];
    __syncthreads();

    int i = blockIdx.x * blockDim.x + threadIdx.x;
    if (i < N_ATOMS) {
        const float* hp = &g_h[(size_t)i * HF];
        float acc = bout[0];
        #pragma unroll
        for (int k = 0; k < HF; k += 4) {
            float4 hv = *reinterpret_cast<const float4*>(&hp[k]);
            acc = fmaf(hv.x, swout[k+0], acc);
            acc = fmaf(hv.y, swout[k+1], acc);
            acc = fmaf(hv.z, swout[k+2], acc);
            acc = fmaf(hv.w, swout[k+3], acc);
        }
        atomicAdd(&sacc[gid[i]], elu1(acc));
    }
    __syncthreads();
    for (int j = threadIdx.x; j < NGRAPH; j += blockDim.x) {
        float v = sacc[j];
        if (v != 0.f) atomicAdd(&out[j], v);
    }
}

// -------- launch --------
extern "C" void kernel_launch(void* const* d_in, const int* in_sizes, int n_in,
                              void* d_out, int out_size) {
    const float* feats = (const float*)d_in[0];
    const int*   src   = (const int*)  d_in[1];
    const int*   dst   = (const int*)  d_in[2];
    const int*   gid   = (const int*)  d_in[3];
    const float* w0    = (const float*)d_in[4];
    const float* b0    = (const float*)d_in[5];
    const float* g0    = (const float*)d_in[6];
    const float* be0   = (const float*)d_in[7];
    const float* wc1   = (const float*)d_in[8];
    const float* bc1   = (const float*)d_in[9];
    const float* w1    = (const float*)d_in[10];
    const float* b1    = (const float*)d_in[11];
    const float* g1    = (const float*)d_in[12];
    const float* be1   = (const float*)d_in[13];
    const float* wc2   = (const float*)d_in[14];
    const float* bc2   = (const float*)d_in[15];
    const float* w2    = (const float*)d_in[16];
    const float* b2    = (const float*)d_in[17];
    const float* g2    = (const float*)d_in[18];
    const float* be2   = (const float*)d_in[19];
    const float* wout  = (const float*)d_in[20];
    const float* bout  = (const float*)d_in[21];
    float* out = (float*)d_out;

    const int TPB = 256;
    int tile_blocks = N_ATOMS / TILE;
    int node_blocks = (N_ATOMS + TPB - 1) / TPB;
    int edge_blocks = (N_EDGES + TPB - 1) / TPB;
    long long sc_threads = (long long)N_EDGES * 4;
    int sc_blocks = (int)((sc_threads + TPB - 1) / TPB);

    // degrees + norms
    zero_deg_kernel<<<(N_ATOMS / 4 + TPB - 1) / TPB, TPB>>>();
    degree_kernel<<<edge_blocks, TPB>>>(src, dst);
    norm_kernel<<<node_blocks, TPB>>>();

    // input MLP -> g_hs (fp16)
    input_mlp_tile<<<tile_blocks, TPB>>>(feats, w0, b0, g0, be0);

    // block 1 (g_m zeroed inside node_block_tile)
    scatter_kernel<<<sc_blocks, TPB>>>(src, dst);
    node_block_tile<0><<<tile_blocks, TPB>>>(wc1, bc1, w1, b1, g1, be1);

    // block 2
    scatter_kernel<<<sc_blocks, TPB>>>(src, dst);
    node_block_tile<1><<<tile_blocks, TPB>>>(wc2, bc2, w2, b2, g2, be2);

    // head + readout
    zero_out_kernel<<<(NGRAPH + TPB - 1) / TPB, TPB>>>(out);
    head_kernel<<<node_blocks, TPB>>>(wout, bout, gid, out);
}

// round 6
// speedup vs baseline: 2.5448x; 1.1115x over previous
#include <cuda_runtime.h>
#include <cuda_fp16.h>
#include <cuda_bf16.h>
#include <math.h>

#define N_ATOMS 1000000
#define N_EDGES 4000000
#define NGRAPH  1024
#define IN_F    64
#define HF      32
#define LN_EPS  1e-5f
#define TILE    64            // nodes per block in node_block tiles
#define TILE_I  128           // nodes per block in input MLP
#define XS_STR  68            // shared row stride for 64-col tile
#define MS_STR  36            // shared row stride for 32-col tiles

// -------- scratch (device globals: zero-initialized at module load) --------
__device__ float  g_deg_out[N_ATOMS];   // invariant: all-zero between launches
__device__ float  g_deg_in[N_ATOMS];    // invariant: all-zero between launches
__device__ float  g_ns[N_ATOMS];
__device__ float  g_nd[N_ATOMS];
__device__ __half g_hs[N_ATOMS * HF];   // h * ns  (fp16 messages)
__device__ __half g_m [N_ATOMS * HF];   // fp16 scatter accumulator (all-zero invariant)

// -------- helpers --------
__device__ __forceinline__ float elu1(float x) { return x > 0.f ? x : expm1f(x); }
__device__ __forceinline__ float sum8(float v) {
    v += __shfl_xor_sync(0xffffffffu, v, 1);
    v += __shfl_xor_sync(0xffffffffu, v, 2);
    v += __shfl_xor_sync(0xffffffffu, v, 4);
    return v;
}

__global__ void zero_out_kernel(float* out) {
    int i = blockIdx.x * blockDim.x + threadIdx.x;
    if (i < NGRAPH) out[i] = 0.f;
}

// -------- degree + norm --------
__global__ void degree_kernel(const int* __restrict__ src, const int* __restrict__ dst) {
    int e = blockIdx.x * blockDim.x + threadIdx.x;
    if (e < N_EDGES) {
        atomicAdd(&g_deg_out[src[e]], 1.f);
        atomicAdd(&g_deg_in [dst[e]], 1.f);
    }
}
// reads degrees, writes norms, restores all-zero invariant on degree arrays
__global__ void norm_kernel() {
    int i = blockIdx.x * blockDim.x + threadIdx.x;
    if (i < N_ATOMS) {
        float dout = g_deg_out[i], din = g_deg_in[i];
        g_ns[i] = dout > 0.f ? rsqrtf(dout) : 0.f;
        g_nd[i] = din  > 0.f ? rsqrtf(din)  : 0.f;
        g_deg_out[i] = 0.f;
        g_deg_in [i] = 0.f;
    }
}

// store 4 consecutive floats as 4 halves (8B)
__device__ __forceinline__ void store_h4(__half* p, float a, float b, float c, float d) {
    __half2 lo = __floats2half2_rn(a, b);
    __half2 hi = __floats2half2_rn(c, d);
    uint2 v;
    v.x = *reinterpret_cast<unsigned*>(&lo);
    v.y = *reinterpret_cast<unsigned*>(&hi);
    *reinterpret_cast<uint2*>(p) = v;
}

// -------- input MLP (tiled, 4 nodes/thread): g_hs = half(elu(LN(feats@w0+b0)) * ns) --------
// 256 threads, 128 nodes/block. thread = (nq [0..31], oq [0..7]);
// nodes {nq, nq+32, nq+64, nq+96}, output cols [4*oq, 4*oq+4).
__global__ __launch_bounds__(256) void input_mlp_tile(
        const float* __restrict__ feats,
        const float* __restrict__ w0,  const float* __restrict__ b0,
        const float* __restrict__ g0,  const float* __restrict__ be0) {
    __shared__ float xs[TILE_I * XS_STR];    // 34.8 KB
    __shared__ float sw[IN_F * HF];          // 8 KB
    int t = threadIdx.x;
    int base = blockIdx.x * TILE_I;

    for (int i = t; i < IN_F * HF / 4; i += 256)
        reinterpret_cast<float4*>(sw)[i] = reinterpret_cast<const float4*>(w0)[i];
    #pragma unroll
    for (int i = t; i < TILE_I * (IN_F / 4); i += 256) {      // 2048 float4
        int n = i >> 4, c = i & 15;
        float4 v = make_float4(0.f, 0.f, 0.f, 0.f);
        if (base + n < N_ATOMS)
            v = reinterpret_cast<const float4*>(feats)[(size_t)(base + n) * 16 + c];
        *reinterpret_cast<float4*>(&xs[n * XS_STR + c * 4]) = v;
    }
    __syncthreads();

    int oq = t & 7, nq = t >> 3;
    float4 bv = reinterpret_cast<const float4*>(b0)[oq];
    float4 acc[4];
    #pragma unroll
    for (int j = 0; j < 4; j++) acc[j] = bv;
    const float* xr[4];
    #pragma unroll
    for (int j = 0; j < 4; j++) xr[j] = &xs[(nq + j * 32) * XS_STR];

    #pragma unroll
    for (int k = 0; k < IN_F; k += 4) {
        float4 wv0 = *reinterpret_cast<const float4*>(&sw[(k+0) * HF + oq * 4]);
        float4 wv1 = *reinterpret_cast<const float4*>(&sw[(k+1) * HF + oq * 4]);
        float4 wv2 = *reinterpret_cast<const float4*>(&sw[(k+2) * HF + oq * 4]);
        float4 wv3 = *reinterpret_cast<const float4*>(&sw[(k+3) * HF + oq * 4]);
        #pragma unroll
        for (int j = 0; j < 4; j++) {
            float4 xv = *reinterpret_cast<const float4*>(&xr[j][k]);
            acc[j].x = fmaf(xv.x, wv0.x, acc[j].x); acc[j].y = fmaf(xv.x, wv0.y, acc[j].y);
            acc[j].z = fmaf(xv.x, wv0.z, acc[j].z); acc[j].w = fmaf(xv.x, wv0.w, acc[j].w);
            acc[j].x = fmaf(xv.y, wv1.x, acc[j].x); acc[j].y = fmaf(xv.y, wv1.y, acc[j].y);
            acc[j].z = fmaf(xv.y, wv1.z, acc[j].z); acc[j].w = fmaf(xv.y, wv1.w, acc[j].w);
            acc[j].x = fmaf(xv.z, wv2.x, acc[j].x); acc[j].y = fmaf(xv.z, wv2.y, acc[j].y);
            acc[j].z = fmaf(xv.z, wv2.z, acc[j].z); acc[j].w = fmaf(xv.z, wv2.w, acc[j].w);
            acc[j].x = fmaf(xv.w, wv3.x, acc[j].x); acc[j].y = fmaf(xv.w, wv3.y, acc[j].y);
            acc[j].z = fmaf(xv.w, wv3.z, acc[j].z); acc[j].w = fmaf(xv.w, wv3.w, acc[j].w);
        }
    }

    float4 gv  = reinterpret_cast<const float4*>(g0)[oq];
    float4 bev = reinterpret_cast<const float4*>(be0)[oq];
    #pragma unroll
    for (int j = 0; j < 4; j++) {
        int node = base + nq + j * 32;
        float4 a = acc[j];
        float mu = sum8(a.x + a.y + a.z + a.w) * (1.f / HF);
        float dx = a.x - mu, dy = a.y - mu, dz = a.z - mu, dw = a.w - mu;
        float var = sum8(dx*dx + dy*dy + dz*dz + dw*dw) * (1.f / HF);
        float r = rsqrtf(var + LN_EPS);
        if (node < N_ATOMS) {
            float s = g_ns[node];
            store_h4(&g_hs[(size_t)node * HF + oq * 4],
                     elu1(dx * r * gv.x + bev.x) * s,
                     elu1(dy * r * gv.y + bev.y) * s,
                     elu1(dz * r * gv.z + bev.z) * s,
                     elu1(dw * r * gv.w + bev.w) * s);
        }
    }
}

// -------- edge scatter: m[dst] += hs[src]  (4 threads/edge, v4.f16x2 RED) --------
__global__ void scatter_kernel(const int* __restrict__ src, const int* __restrict__ dst) {
    long long idx = (long long)blockIdx.x * blockDim.x + threadIdx.x;
    if (idx >= (long long)N_EDGES * 4) return;
    int e = (int)(idx >> 2);
    int p = ((int)idx & 3) * 8;
    int s = __ldg(&src[e]);
    int d = __ldg(&dst[e]);
    uint4 v = __ldg(reinterpret_cast<const uint4*>(&g_hs[(size_t)s * HF + p]));
    __half* mp = &g_m[(size_t)d * HF + p];
    asm volatile("red.global.add.noftz.v4.f16x2 [%0], {%1, %2, %3, %4};"
                 :: "l"(mp), "r"(v.x), "r"(v.y), "r"(v.z), "r"(v.w) : "memory");
}

// -------- conv epilogue + node MLP block (tiled) --------
// MODE 0: out -> g_hs (half, *ns). MODE 1: fused head -> per-graph sums in `out`.
// Both modes zero g_m after consuming it.
template<int MODE>
__global__ __launch_bounds__(256) void node_block_tile(
        const float* __restrict__ wc, const float* __restrict__ bc,
        const float* __restrict__ w,  const float* __restrict__ b,
        const float* __restrict__ g,  const float* __restrict__ be,
        const float* __restrict__ wout, const float* __restrict__ bout,
        const int* __restrict__ gid, float* __restrict__ out) {
    __shared__ float ms[TILE * MS_STR];
    __shared__ float ts[TILE * MS_STR];
    __shared__ float swc[HF * HF];
    __shared__ float sw [HF * HF];
    __shared__ float sacc[NGRAPH];
    int t = threadIdx.x;
    int base = blockIdx.x * TILE;

    for (int i = t; i < HF * HF; i += 256) { swc[i] = wc[i]; sw[i] = w[i]; }
    if (MODE == 1)
        for (int i = t; i < NGRAPH; i += 256) sacc[i] = 0.f;
    // load m tile (half -> float, *nd) and restore all-zero invariant
    {
        int n = t >> 2, c = t & 3;
        uint4* gp = reinterpret_cast<uint4*>(&g_m[(size_t)(base + n) * HF + c * 8]);
        uint4 v = *gp;
        float ndv = g_nd[base + n];
        float* mrow = &ms[n * MS_STR + c * 8];
        __half2 h;
        h = *reinterpret_cast<__half2*>(&v.x); float2 f0 = __half22float2(h);
        h = *reinterpret_cast<__half2*>(&v.y); float2 f1 = __half22float2(h);
        h = *reinterpret_cast<__half2*>(&v.z); float2 f2 = __half22float2(h);
        h = *reinterpret_cast<__half2*>(&v.w); float2 f3 = __half22float2(h);
        mrow[0] = f0.x * ndv; mrow[1] = f0.y * ndv;
        mrow[2] = f1.x * ndv; mrow[3] = f1.y * ndv;
        mrow[4] = f2.x * ndv; mrow[5] = f2.y * ndv;
        mrow[6] = f3.x * ndv; mrow[7] = f3.y * ndv;
        *gp = make_uint4(0u, 0u, 0u, 0u);
    }
    __syncthreads();

    int oq = t & 7, nq = t >> 3;

    // GEMM1: ts = elu(ms @ wc + bc)
    {
        float4 bv = reinterpret_cast<const float4*>(bc)[oq];
        float4 a0 = bv, a1 = bv;
        const float* x0 = &ms[nq * MS_STR];
        const float* x1 = &ms[(nq + 32) * MS_STR];
        #pragma unroll
        for (int k = 0; k < HF; k += 4) {
            float4 wv0 = *reinterpret_cast<const float4*>(&swc[(k+0) * HF + oq * 4]);
            float4 wv1 = *reinterpret_cast<const float4*>(&swc[(k+1) * HF + oq * 4]);
            float4 wv2 = *reinterpret_cast<const float4*>(&swc[(k+2) * HF + oq * 4]);
            float4 wv3 = *reinterpret_cast<const float4*>(&swc[(k+3) * HF + oq * 4]);
            float4 xv0 = *reinterpret_cast<const float4*>(&x0[k]);
            float4 xv1 = *reinterpret_cast<const float4*>(&x1[k]);
            a0.x = fmaf(xv0.x, wv0.x, a0.x); a0.y = fmaf(xv0.x, wv0.y, a0.y); a0.z = fmaf(xv0.x, wv0.z, a0.z); a0.w = fmaf(xv0.x, wv0.w, a0.w);
            a0.x = fmaf(xv0.y, wv1.x, a0.x); a0.y = fmaf(xv0.y, wv1.y, a0.y); a0.z = fmaf(xv0.y, wv1.z, a0.z); a0.w = fmaf(xv0.y, wv1.w, a0.w);
            a0.x = fmaf(xv0.z, wv2.x, a0.x); a0.y = fmaf(xv0.z, wv2.y, a0.y); a0.z = fmaf(xv0.z, wv2.z, a0.z); a0.w = fmaf(xv0.z, wv2.w, a0.w);
            a0.x = fmaf(xv0.w, wv3.x, a0.x); a0.y = fmaf(xv0.w, wv3.y, a0.y); a0.z = fmaf(xv0.w, wv3.z, a0.z); a0.w = fmaf(xv0.w, wv3.w, a0.w);
            a1.x = fmaf(xv1.x, wv0.x, a1.x); a1.y = fmaf(xv1.x, wv0.y, a1.y); a1.z = fmaf(xv1.x, wv0.z, a1.z); a1.w = fmaf(xv1.x, wv0.w, a1.w);
            a1.x = fmaf(xv1.y, wv1.x, a1.x); a1.y = fmaf(xv1.y, wv1.y, a1.y); a1.z = fmaf(xv1.y, wv1.z, a1.z); a1.w = fmaf(xv1.y, wv1.w, a1.w);
            a1.x = fmaf(xv1.z, wv2.x, a1.x); a1.y = fmaf(xv1.z, wv2.y, a1.y); a1.z = fmaf(xv1.z, wv2.z, a1.z); a1.w = fmaf(xv1.z, wv2.w, a1.w);
            a1.x = fmaf(xv1.w, wv3.x, a1.x); a1.y = fmaf(xv1.w, wv3.y, a1.y); a1.z = fmaf(xv1.w, wv3.z, a1.z); a1.w = fmaf(xv1.w, wv3.w, a1.w);
        }
        float4 o0, o1;
        o0.x = elu1(a0.x); o0.y = elu1(a0.y); o0.z = elu1(a0.z); o0.w = elu1(a0.w);
        o1.x = elu1(a1.x); o1.y = elu1(a1.y); o1.z = elu1(a1.z); o1.w = elu1(a1.w);
        *reinterpret_cast<float4*>(&ts[nq * MS_STR + oq * 4]) = o0;
        *reinterpret_cast<float4*>(&ts[(nq + 32) * MS_STR + oq * 4]) = o1;
    }
    __syncthreads();

    // GEMM2: u = ts @ w + b ; LN ; ELU ; output
    {
        float4 bv = reinterpret_cast<const float4*>(b)[oq];
        float4 a0 = bv, a1 = bv;
        const float* x0 = &ts[nq * MS_STR];
        const float* x1 = &ts[(nq + 32) * MS_STR];
        #pragma unroll
        for (int k = 0; k < HF; k += 4) {
            float4 wv0 = *reinterpret_cast<const float4*>(&sw[(k+0) * HF + oq * 4]);
            float4 wv1 = *reinterpret_cast<const float4*>(&sw[(k+1) * HF + oq * 4]);
            float4 wv2 = *reinterpret_cast<const float4*>(&sw[(k+2) * HF + oq * 4]);
            float4 wv3 = *reinterpret_cast<const float4*>(&sw[(k+3) * HF + oq * 4]);
            float4 xv0 = *reinterpret_cast<const float4*>(&x0[k]);
            float4 xv1 = *reinterpret_cast<const float4*>(&x1[k]);
            a0.x = fmaf(xv0.x, wv0.x, a0.x); a0.y = fmaf(xv0.x, wv0.y, a0.y); a0.z = fmaf(xv0.x, wv0.z, a0.z); a0.w = fmaf(xv0.x, wv0.w, a0.w);
            a0.x = fmaf(xv0.y, wv1.x, a0.x); a0.y = fmaf(xv0.y, wv1.y, a0.y); a0.z = fmaf(xv0.y, wv1.z, a0.z); a0.w = fmaf(xv0.y, wv1.w, a0.w);
            a0.x = fmaf(xv0.z, wv2.x, a0.x); a0.y = fmaf(xv0.z, wv2.y, a0.y); a0.z = fmaf(xv0.z, wv2.z, a0.z); a0.w = fmaf(xv0.z, wv2.w, a0.w);
            a0.x = fmaf(xv0.w, wv3.x, a0.x); a0.y = fmaf(xv0.w, wv3.y, a0.y); a0.z = fmaf(xv0.w, wv3.z, a0.z); a0.w = fmaf(xv0.w, wv3.w, a0.w);
            a1.x = fmaf(xv1.x, wv0.x, a1.x); a1.y = fmaf(xv1.x, wv0.y, a1.y); a1.z = fmaf(xv1.x, wv0.z, a1.z); a1.w = fmaf(xv1.x, wv0.w, a1.w);
            a1.x = fmaf(xv1.y, wv1.x, a1.x); a1.y = fmaf(xv1.y, wv1.y, a1.y); a1.z = fmaf(xv1.y, wv1.z, a1.z); a1.w = fmaf(xv1.y, wv1.w, a1.w);
            a1.x = fmaf(xv1.z, wv2.x, a1.x); a1.y = fmaf(xv1.z, wv2.y, a1.y); a1.z = fmaf(xv1.z, wv2.z, a1.z); a1.w = fmaf(xv1.z, wv2.w, a1.w);
            a1.x = fmaf(xv1.w, wv3.x, a1.x); a1.y = fmaf(xv1.w, wv3.y, a1.y); a1.z = fmaf(xv1.w, wv3.z, a1.z); a1.w = fmaf(xv1.w, wv3.w, a1.w);
        }
        float4 gv  = reinterpret_cast<const float4*>(g)[oq];
        float4 bev = reinterpret_cast<const float4*>(be)[oq];
        float4 wov; float bo = 0.f;
        if (MODE == 1) { wov = reinterpret_cast<const float4*>(wout)[oq]; bo = bout[0]; }
        #pragma unroll
        for (int nn = 0; nn < 2; nn++) {
            float4 a = nn ? a1 : a0;
            int node = base + nq + nn * 32;
            float mu = sum8(a.x + a.y + a.z + a.w) * (1.f / HF);
            float dx = a.x - mu, dy = a.y - mu, dz = a.z - mu, dw = a.w - mu;
            float var = sum8(dx*dx + dy*dy + dz*dz + dw*dw) * (1.f / HF);
            float r = rsqrtf(var + LN_EPS);
            float hx = elu1(dx * r * gv.x + bev.x);
            float hy = elu1(dy * r * gv.y + bev.y);
            float hz = elu1(dz * r * gv.z + bev.z);
            float hw = elu1(dw * r * gv.w + bev.w);
            if (MODE == 0) {
                float s = g_ns[node];
                store_h4(&g_hs[(size_t)node * HF + oq * 4], hx * s, hy * s, hz * s, hw * s);
            } else {
                // fused head: v = elu(h . wout + bout); per-graph accumulate
                float partial = hx * wov.x + hy * wov.y + hz * wov.z + hw * wov.w;
                float dot = sum8(partial) + bo;
                if (oq == 0) atomicAdd(&sacc[gid[node]], elu1(dot));
            }
        }
    }
    if (MODE == 1) {
        __syncthreads();
        for (int j = t; j < NGRAPH; j += 256) {
            float v = sacc[j];
            if (v != 0.f) atomicAdd(&out[j], v);
        }
    }
}

// -------- launch --------
extern "C" void kernel_launch(void* const* d_in, const int* in_sizes, int n_in,
                              void* d_out, int out_size) {
    const float* feats = (const float*)d_in[0];
    const int*   src   = (const int*)  d_in[1];
    const int*   dst   = (const int*)  d_in[2];
    const int*   gid   = (const int*)  d_in[3];
    const float* w0    = (const float*)d_in[4];
    const float* b0    = (const float*)d_in[5];
    const float* g0    = (const float*)d_in[6];
    const float* be0   = (const float*)d_in[7];
    const float* wc1   = (const float*)d_in[8];
    const float* bc1   = (const float*)d_in[9];
    const float* w1    = (const float*)d_in[10];
    const float* b1    = (const float*)d_in[11];
    const float* g1    = (const float*)d_in[12];
    const float* be1   = (const float*)d_in[13];
    const float* wc2   = (const float*)d_in[14];
    const float* bc2   = (const float*)d_in[15];
    const float* w2    = (const float*)d_in[16];
    const float* b2    = (const float*)d_in[17];
    const float* g2    = (const float*)d_in[18];
    const float* be2   = (const float*)d_in[19];
    const float* wout  = (const float*)d_in[20];
    const float* bout  = (const float*)d_in[21];
    float* out = (float*)d_out;

    const int TPB = 256;
    int tile_blocks   = N_ATOMS / TILE;                        // 15625
    int tile_i_blocks = (N_ATOMS + TILE_I - 1) / TILE_I;       // 7813
    int node_blocks   = (N_ATOMS + TPB - 1) / TPB;
    int edge_blocks   = (N_EDGES + TPB - 1) / TPB;
    long long sc_threads = (long long)N_EDGES * 4;
    int sc_blocks = (int)((sc_threads + TPB - 1) / TPB);

    // degrees + norms (deg arrays re-zeroed inside norm_kernel)
    degree_kernel<<<edge_blocks, TPB>>>(src, dst);
    norm_kernel<<<node_blocks, TPB>>>();

    // input MLP -> g_hs (fp16)
    input_mlp_tile<<<tile_i_blocks, TPB>>>(feats, w0, b0, g0, be0);

    // block 1 (g_m zeroed inside node_block_tile)
    scatter_kernel<<<sc_blocks, TPB>>>(src, dst);
    node_block_tile<0><<<tile_blocks, TPB>>>(wc1, bc1, w1, b1, g1, be1, wout, bout, gid, out);

    // block 2 + fused head
    zero_out_kernel<<<(NGRAPH + TPB - 1) / TPB, TPB>>>(out);
    scatter_kernel<<<sc_blocks, TPB>>>(src, dst);
    node_block_tile<1><<<tile_blocks, TPB>>>(wc2, bc2, w2, b2, g2, be2, wout, bout, gid, out);
}